// round 1
// baseline (speedup 1.0000x reference)
#include <cuda_runtime.h>

#define BATCH   32
#define CDIM    192
#define PDIM    3136
#define TP      8            // patches per block (PDIM/TP = 392 blocks)
#define SSTR    257          // smem c-stride in floats (8*257 % 32 == 8 -> conflict-free d loads)
#define THREADS 512
#define NTILE   ((CDIM/8)*((CDIM/8)+1)/2)   // 300 lower-triangle 8x8 tiles
#define SMEM_BYTES (CDIM * SSTR * 4)        // 197376 B

__global__ __launch_bounds__(THREADS, 1)
void padim_kernel(const float* __restrict__ emb,
                  const float* __restrict__ means_in,
                  const float* __restrict__ cov_in,
                  float* __restrict__ out_means,
                  float* __restrict__ out_cov)
{
    extern __shared__ float sm[];   // sm[c*SSTR + b*TP + ii]
    const int i0  = blockIdx.x * TP;
    const int tid = threadIdx.x;

    // ---- Stage embeddings slice [C][B][TP] into smem.
    // Each (b,c) pair = 8 consecutive floats at emb[b*C*P + c*P + i0] (32B aligned sector).
    for (int p = tid; p < BATCH * CDIM; p += THREADS) {
        const int b = p / CDIM;
        const int c = p - b * CDIM;
        const float4* g = reinterpret_cast<const float4*>(
            emb + (size_t)b * CDIM * PDIM + (size_t)c * PDIM + i0);
        float4 v0 = g[0];
        float4 v1 = g[1];
        float* s = sm + c * SSTR + b * TP;
        s[0] = v0.x; s[1] = v0.y; s[2] = v0.z; s[3] = v0.w;
        s[4] = v1.x; s[5] = v1.y; s[6] = v1.z; s[7] = v1.w;
    }
    __syncthreads();

    // ---- Means: out_means[i, c] = means_in[i, c] + sum_b emb[b, c, i]
    for (int p = tid; p < CDIM * TP; p += THREADS) {
        const int c  = p / TP;
        const int ii = p - c * TP;
        const float* s = sm + c * SSTR + ii;
        float ssum = 0.f;
        #pragma unroll
        for (int b = 0; b < BATCH; b++) ssum += s[b * TP];
        const size_t idx = (size_t)(i0 + ii) * CDIM + c;
        out_means[idx] = means_in[idx] + ssum;
    }

    // ---- Covariance: lower-triangle 8x8 tiles, mirrored in registers.
    const int wid  = tid >> 5;
    const int lane = tid & 31;
    const int ii   = lane >> 2;    // patch within block: 0..7
    const int q    = lane & 3;     // tile slot within warp-task: 0..3
    const int NW   = THREADS / 32; // 16 warps
    const int NWT  = NTILE / 4;    // 75 warp-tasks (exact)

    for (int w = wid; w < NWT; w += NW) {
        const int t = w * 4 + q;   // tile id in [0, 300)

        // tile id -> (tc, td), td <= tc
        int tc = (int)((sqrtf(8.0f * (float)t + 1.0f) - 1.0f) * 0.5f);
        while ((tc + 1) * (tc + 2) / 2 <= t) tc++;
        while (tc * (tc + 1) / 2 > t) tc--;
        const int td = t - tc * (tc + 1) / 2;

        float acc[8][8];
        #pragma unroll
        for (int u = 0; u < 8; u++)
            #pragma unroll
            for (int v = 0; v < 8; v++) acc[u][v] = 0.f;

        const float* sa = sm + (tc * 8) * SSTR + ii;
        const float* sb = sm + (td * 8) * SSTR + ii;

        #pragma unroll 2
        for (int b = 0; b < BATCH; b++) {
            const int bo = b * TP;
            float av[8], bv[8];
            #pragma unroll
            for (int u = 0; u < 8; u++) av[u] = sa[u * SSTR + bo];
            #pragma unroll
            for (int v = 0; v < 8; v++) bv[v] = sb[v * SSTR + bo];
            #pragma unroll
            for (int u = 0; u < 8; u++)
                #pragma unroll
                for (int v = 0; v < 8; v++)
                    acc[u][v] = fmaf(av[u], bv[v], acc[u][v]);
        }

        const size_t cov_base = (size_t)(i0 + ii) * CDIM * CDIM;

        // Write tile (tc, td): rows c = tc*8+u, cols d = td*8+v  (fused += cov_in)
        #pragma unroll
        for (int u = 0; u < 8; u++) {
            const size_t off = cov_base + (size_t)(tc * 8 + u) * CDIM + td * 8;
            const float4* gin = reinterpret_cast<const float4*>(cov_in + off);
            float4* gout      = reinterpret_cast<float4*>(out_cov + off);
            float4 c0 = gin[0];
            float4 c1 = gin[1];
            c0.x += acc[u][0]; c0.y += acc[u][1]; c0.z += acc[u][2]; c0.w += acc[u][3];
            c1.x += acc[u][4]; c1.y += acc[u][5]; c1.z += acc[u][6]; c1.w += acc[u][7];
            gout[0] = c0;
            gout[1] = c1;
        }

        // Mirror tile (td, tc) with transposed accumulators (skip for diagonal tiles)
        if (tc != td) {
            #pragma unroll
            for (int v = 0; v < 8; v++) {
                const size_t off = cov_base + (size_t)(td * 8 + v) * CDIM + tc * 8;
                const float4* gin = reinterpret_cast<const float4*>(cov_in + off);
                float4* gout      = reinterpret_cast<float4*>(out_cov + off);
                float4 c0 = gin[0];
                float4 c1 = gin[1];
                c0.x += acc[0][v]; c0.y += acc[1][v]; c0.z += acc[2][v]; c0.w += acc[3][v];
                c1.x += acc[4][v]; c1.y += acc[5][v]; c1.z += acc[6][v]; c1.w += acc[7][v];
                gout[0] = c0;
                gout[1] = c1;
            }
        }
    }
}

extern "C" void kernel_launch(void* const* d_in, const int* in_sizes, int n_in,
                              void* d_out, int out_size)
{
    const float* emb   = (const float*)d_in[0];  // [B, C, P]
    const float* means = (const float*)d_in[1];  // [P, C]
    const float* cov   = (const float*)d_in[2];  // [P, C, C]
    float* out       = (float*)d_out;
    float* out_means = out;                              // [P, C]
    float* out_cov   = out + (size_t)PDIM * CDIM;        // [P, C, C]

    cudaFuncSetAttribute(padim_kernel,
                         cudaFuncAttributeMaxDynamicSharedMemorySize, SMEM_BYTES);
    padim_kernel<<<PDIM / TP, THREADS, SMEM_BYTES>>>(emb, means, cov,
                                                     out_means, out_cov);
}